// round 11
// baseline (speedup 1.0000x reference)
#include <cuda_runtime.h>

// GRU4Rec user module: ragged GRU(128) -> dense(128) -> L2 normalize.
// Inputs: x f32[T,128], offset i32[B] (i64 auto-detect), W_ih f32[384,128],
//         W_hh f32[384,128], W_dense f32[128,128], b_dense f32[128]
// Output: f32[B,128]
//
// R11: k_xproj reverted to proven R7 (4-token tiles). k_rec v3: split-row,
// 768 threads / 24 warps (half W_hh row per thread -> 32-deep FMA chains),
// partials combined in smem; rcp.approx-based activations.

#define DIMD 128
#define DIMH 128
#define G3   384
#define MAXB 4096
#define MAXLEN 200

__device__ float g_xproj[(size_t)2048 * MAXLEN * G3];
__device__ int g_off[MAXB];
__device__ int g_len[MAXB];
__device__ int g_order[MAXB];

__device__ __forceinline__ void ffma2(unsigned long long &acc,
                                      unsigned long long a,
                                      unsigned long long b) {
    asm("fma.rn.f32x2 %0, %1, %2, %0;" : "+l"(acc) : "l"(a), "l"(b));
}
__device__ __forceinline__ float f2lo(unsigned long long v) {
    return __uint_as_float((unsigned int)v);
}
__device__ __forceinline__ float f2hi(unsigned long long v) {
    return __uint_as_float((unsigned int)(v >> 32));
}
__device__ __forceinline__ float rcp_approx(float x) {
    float r;
    asm("rcp.approx.f32 %0, %1;" : "=f"(r) : "f"(x));
    return r;
}
__device__ __forceinline__ float fast_sigmoid(float v) {
    return rcp_approx(1.0f + __expf(-v));
}
__device__ __forceinline__ float fast_tanh(float v) {
    float av = fabsf(v);
    float e = __expf(-2.0f * av);
    float m = (1.0f - e) * rcp_approx(1.0f + e);
    return copysignf(m, v);
}
__device__ __forceinline__ int load_off(const void* p, int i, bool is64) {
    return is64 ? (int)((const long long*)p)[i] : ((const int*)p)[i];
}

// ---------------------------------------------------------------------------
// K0: offsets/lengths + counting sort of sequence indices by length.
// ---------------------------------------------------------------------------
__global__ void k_sort(const void* __restrict__ off_raw, int T, int B) {
    __shared__ int s_cnt[MAXLEN + 1];
    const int tid = threadIdx.x;
    const bool is64 = (B > 1) && (((const int*)off_raw)[1] == 0);

    for (int i = tid; i <= MAXLEN; i += blockDim.x) s_cnt[i] = 0;
    __syncthreads();

    for (int i = tid; i < B; i += blockDim.x) {
        int o  = load_off(off_raw, i, is64);
        int oe = (i + 1 < B) ? load_off(off_raw, i + 1, is64) : T;
        int l = oe - o;
        if (o < 0) o = 0;
        if (l < 0) l = 0;
        if (l > MAXLEN) l = MAXLEN;
        g_off[i] = o;
        g_len[i] = l;
        atomicAdd(&s_cnt[l], 1);
    }
    __syncthreads();

    if (tid == 0) {
        int run = 0;
        for (int j = 0; j <= MAXLEN; j++) { int c = s_cnt[j]; s_cnt[j] = run; run += c; }
    }
    __syncthreads();

    for (int i = tid; i < B; i += blockDim.x) {
        int pos = atomicAdd(&s_cnt[g_len[i]], 1);
        g_order[pos] = i;
    }
}

// ---------------------------------------------------------------------------
// K1: x_proj = x @ W_ih^T. 4-token tiles (exact R7 version, proven fastest).
// ---------------------------------------------------------------------------
__global__ __launch_bounds__(384, 1)
void k_xproj(const float* __restrict__ x,
             const float* __restrict__ W_ih,
             int T, int chunk) {
    const int g = threadIdx.x;

    int t0 = blockIdx.x * chunk;
    int t1 = min(T, t0 + chunk);
    if (t0 >= t1) return;  // uniform across block

    unsigned long long Wr[64];
    {
        const unsigned long long* Wp =
            (const unsigned long long*)(W_ih + (size_t)g * DIMD);
        #pragma unroll
        for (int j = 0; j < 64; j++) Wr[j] = Wp[j];
    }

    __shared__ __align__(16) float sx[2][4][DIMD];

    if (g < 128) {
        int tk = t0 + (g >> 5);
        if (tk < t1)
            ((float4*)sx[0][g >> 5])[g & 31] =
                ((const float4*)x)[(size_t)tk * 32 + (g & 31)];
    }
    __syncthreads();

    int buf = 0;
    for (int ts = t0; ts < t1; ts += 4) {
        if (g < 128) {
            int tk = ts + 4 + (g >> 5);
            if (tk < t1)
                ((float4*)sx[buf ^ 1][g >> 5])[g & 31] =
                    ((const float4*)x)[(size_t)tk * 32 + (g & 31)];
        }

        unsigned long long a0[4], a1[4];
        #pragma unroll
        for (int k = 0; k < 4; k++) { a0[k] = 0ull; a1[k] = 0ull; }

        const ulonglong2* hp0 = (const ulonglong2*)sx[buf][0];
        const ulonglong2* hp1 = (const ulonglong2*)sx[buf][1];
        const ulonglong2* hp2 = (const ulonglong2*)sx[buf][2];
        const ulonglong2* hp3 = (const ulonglong2*)sx[buf][3];
        #pragma unroll
        for (int j = 0; j < 32; j++) {
            ulonglong2 v0 = hp0[j], v1 = hp1[j], v2 = hp2[j], v3 = hp3[j];
            ffma2(a0[0], Wr[2 * j], v0.x);  ffma2(a1[0], Wr[2 * j + 1], v0.y);
            ffma2(a0[1], Wr[2 * j], v1.x);  ffma2(a1[1], Wr[2 * j + 1], v1.y);
            ffma2(a0[2], Wr[2 * j], v2.x);  ffma2(a1[2], Wr[2 * j + 1], v2.y);
            ffma2(a0[3], Wr[2 * j], v3.x);  ffma2(a1[3], Wr[2 * j + 1], v3.y);
        }
        #pragma unroll
        for (int k = 0; k < 4; k++) {
            int tk = ts + k;
            if (tk < t1) {
                float s = (f2lo(a0[k]) + f2hi(a0[k])) + (f2lo(a1[k]) + f2hi(a1[k]));
                g_xproj[(size_t)tk * G3 + g] = s;
            }
        }

        __syncthreads();
        buf ^= 1;
    }
}

// ---------------------------------------------------------------------------
// K2 v3: GRU recurrence, 2 length-sorted sequences per block, 768 threads.
// Thread (r, half) owns half of W_hh row r (64 weights = 32 ull regs).
// Per step: 2 chains of 32 dependent FFMA2 (vs 64 before), partials combined
// in smem by the 256 gate threads. 24 warps/SM for latency hiding.
// ---------------------------------------------------------------------------
__global__ __launch_bounds__(768, 1)
void k_rec(const float* __restrict__ W_hh,
           const float* __restrict__ W_dense,
           const float* __restrict__ b_dense,
           float* __restrict__ out,
           int B) {
    const int i = threadIdx.x;
    const int h = (i >= 384) ? 1 : 0;   // which half of the row
    const int r = i - h * 384;          // row 0..383

    const int i0 = 2 * blockIdx.x;
    const int seq0 = g_order[i0];
    const int seq1 = (i0 + 1 < B) ? g_order[i0 + 1] : -1;

    const int len0 = g_len[seq0];
    const int len1 = (seq1 >= 0) ? g_len[seq1] : 0;
    const int lmax = max(len0, len1);

    // half-row weights: W_hh[r][h*64 .. h*64+63]
    unsigned long long Wr[32];
    {
        const unsigned long long* Wp =
            (const unsigned long long*)(W_hh + (size_t)r * DIMH + h * 64);
        #pragma unroll
        for (int j = 0; j < 32; j++) Wr[j] = Wp[j];
    }

    __shared__ __align__(16) float sh_h[2][DIMH];
    __shared__ float sh_part[2][2][G3];    // [seq][half][row]
    __shared__ float sh_xgn[2][DIMH];
    __shared__ float sred[8];

    if (i < 256) sh_h[i >> 7][i & 127] = 0.0f;
    __syncthreads();

    // xv streaming: half 0 threads stream seq0's xg row r, half 1 -> seq1
    const int mylen = h ? len1 : len0;
    const int myoff = h ? ((seq1 >= 0) ? g_off[seq1] : 0) : g_off[seq0];
    const float* xg = g_xproj + (size_t)myoff * G3 + r;
    float xv = (0 < mylen) ? xg[0] : 0.0f;

    for (int t = 0; t < lmax; t++) {
        float xn = (t + 1 < mylen) ? xg[(size_t)(t + 1) * G3] : 0.0f;

        unsigned long long a0 = 0ull, a1 = 0ull;
        const ulonglong2* hp0 = ((const ulonglong2*)sh_h[0]) + h * 16;
        const ulonglong2* hp1 = ((const ulonglong2*)sh_h[1]) + h * 16;
        #pragma unroll
        for (int j = 0; j < 16; j++) {
            ulonglong2 v0 = hp0[j];            // broadcast LDS.128
            ulonglong2 v1 = hp1[j];
            ffma2(a0, Wr[2 * j],     v0.x);
            ffma2(a0, Wr[2 * j + 1], v0.y);
            ffma2(a1, Wr[2 * j],     v1.x);
            ffma2(a1, Wr[2 * j + 1], v1.y);
        }
        float d0 = f2lo(a0) + f2hi(a0);
        float d1 = f2lo(a1) + f2hi(a1);

        // fold my xv (seq h) into my half's partial; n-rows keep xg separate
        {
            float dm = h ? d1 : d0;
            if (r < 2 * DIMH) dm += xv;
            else              sh_xgn[h][r - 2 * DIMH] = xv;
            if (h) d1 = dm; else d0 = dm;
        }
        sh_part[0][h][r] = d0;
        sh_part[1][h][r] = d1;
        __syncthreads();

        if (i < 256) {                         // gate threads: s = i>>7, j = i&127
            int s = i >> 7;
            int j = i & 127;
            int ls = s ? len1 : len0;
            if (t < ls) {
                float rp  = sh_part[s][0][j]           + sh_part[s][1][j];
                float zp  = sh_part[s][0][j + 128]     + sh_part[s][1][j + 128];
                float hgn = sh_part[s][0][j + 256]     + sh_part[s][1][j + 256];
                float rg = fast_sigmoid(rp);
                float zg = fast_sigmoid(zp);
                float n  = fast_tanh(fmaf(rg, hgn, sh_xgn[s][j]));
                float ho = sh_h[s][j];
                sh_h[s][j] = fmaf(zg, ho - n, n);   // (1-z)*n + z*h
            }
        }
        __syncthreads();

        xv = xn;
    }

    // dense + L2 normalize: threads 0..255 (s = i>>7, d = i&127)
    float val = 0.0f;
    const int s = i >> 7;
    const int d = i & 127;
    if (i < 256) {
        unsigned long long a0 = 0ull, a1 = 0ull;
        const unsigned long long* Wd =
            (const unsigned long long*)(W_dense + (size_t)d * DIMH);
        const ulonglong2* hp = (const ulonglong2*)sh_h[s];
        #pragma unroll
        for (int j = 0; j < 32; j++) {
            ulonglong2 hv = hp[j];
            ffma2(a0, Wd[2 * j],     hv.x);
            ffma2(a1, Wd[2 * j + 1], hv.y);
        }
        val = (f2lo(a0) + f2hi(a0)) + (f2lo(a1) + f2hi(a1)) + b_dense[d];

        float ss = val * val;
        #pragma unroll
        for (int sh = 16; sh > 0; sh >>= 1)
            ss += __shfl_xor_sync(0xffffffffu, ss, sh);
        if ((i & 31) == 0) sred[i >> 5] = ss;   // warps 0..7
    }
    __syncthreads();

    if (i < 256) {
        int base = s * 4;
        float ss = sred[base] + sred[base + 1] + sred[base + 2] + sred[base + 3];
        float nrm = fmaxf(sqrtf(ss), 1e-12f);
        int seq = s ? seq1 : seq0;
        if (seq >= 0)
            out[(size_t)seq * DIMD + d] = val / nrm;
    }
}

// ---------------------------------------------------------------------------
extern "C" void kernel_launch(void* const* d_in, const int* in_sizes, int n_in,
                              void* d_out, int out_size) {
    const float* x       = (const float*)d_in[0];
    const void*  off     = d_in[1];                   // int32 or int64
    const float* W_ih    = (const float*)d_in[2];
    const float* W_hh    = (const float*)d_in[3];
    const float* W_dense = (const float*)d_in[4];
    const float* b_dense = (const float*)d_in[5];
    float*       out     = (float*)d_out;

    const int T = in_sizes[0] / DIMD;   // total tokens
    const int B = out_size / DIMD;      // number of sequences

    const int G1 = 1184;                // 8 waves at 1 block/SM on 148 SMs
    const int chunk = (T + G1 - 1) / G1;
    k_xproj<<<G1, 384>>>(x, W_ih, T, chunk);

    k_sort<<<1, 256>>>(off, T, B);

    const int G2 = (B + 1) / 2;
    k_rec<<<G2, 768>>>(W_hh, W_dense, b_dense, out, B);
}